// round 2
// baseline (speedup 1.0000x reference)
#include <cuda_runtime.h>
#include <cuda_bf16.h>

#define N_NODES 100000
#define N_EDGES 1600000
#define D_FEAT  64
#define UNITS   64

// Scratch (allocation-free rule: __device__ globals)
__device__ float g_deg[N_NODES];
__device__ float4 g_norm[N_NODES * (D_FEAT / 4)];   // 25.6 MB, normalized features

// ---------------------------------------------------------------------------
// K1: zero pooled (d_out used as accumulator) and degree
// ---------------------------------------------------------------------------
__global__ void k_zero(float4* __restrict__ pooled4) {
    int i = blockIdx.x * blockDim.x + threadIdx.x;
    if (i < N_NODES * (D_FEAT / 4)) pooled4[i] = make_float4(0.f, 0.f, 0.f, 0.f);
    if (i < N_NODES) g_deg[i] = 0.f;
}

// ---------------------------------------------------------------------------
// K2: in-degree via atomics on target
// ---------------------------------------------------------------------------
__global__ void k_degree(const int* __restrict__ target) {
    int e = blockIdx.x * blockDim.x + threadIdx.x;
    if (e < N_EDGES) atomicAdd(&g_deg[target[e]], 1.0f);
}

// ---------------------------------------------------------------------------
// K3: normalized = rsqrt(deg)[:,None] * x   (float4 lanes, 16 per node)
// ---------------------------------------------------------------------------
__global__ void k_normalize(const float4* __restrict__ x4) {
    int i = blockIdx.x * blockDim.x + threadIdx.x;
    if (i >= N_NODES * (D_FEAT / 4)) return;
    int node = i >> 4;
    float s = rsqrtf(g_deg[node]);
    float4 v = x4[i];
    v.x *= s; v.y *= s; v.z *= s; v.w *= s;
    g_norm[i] = v;
}

// ---------------------------------------------------------------------------
// K4: scatter-add  pooled[target] += norm[source]
//     16 threads per edge, each handles one float4 (4 features)
// ---------------------------------------------------------------------------
__global__ void k_scatter(const int* __restrict__ source,
                          const int* __restrict__ target,
                          float4* __restrict__ pooled4) {
    int i = blockIdx.x * blockDim.x + threadIdx.x;
    if (i >= N_EDGES * 16) return;
    int e   = i >> 4;
    int sub = i & 15;
    int s = __ldg(&source[e]);
    int t = __ldg(&target[e]);
    float4 v = g_norm[s * 16 + sub];
    atomicAdd(&pooled4[t * 16 + sub], v);
}

// ---------------------------------------------------------------------------
// K5: out = relu( (rsqrt(deg)[:,None] * pooled) @ W + b )   in-place on d_out
//     8 nodes per block, 512 threads: tid%64 = output unit, tid/64 = row.
// ---------------------------------------------------------------------------
__global__ __launch_bounds__(512) void k_gemm(const float* __restrict__ W,
                                              const float* __restrict__ b,
                                              float* __restrict__ out) {
    __shared__ float sW[D_FEAT][UNITS];   // 16 KB
    __shared__ float sP[8][D_FEAT];       // 2 KB
    __shared__ float sB[UNITS];

    int tid = threadIdx.x;
    int u = tid & 63;        // output unit
    int r = tid >> 6;        // local row 0..7

    // cooperative load of W (4096 floats / 512 threads = 8 each) and b
    #pragma unroll
    for (int i = 0; i < 8; i++) {
        int idx = tid + i * 512;
        sW[idx >> 6][idx & 63] = W[idx];
    }
    if (tid < UNITS) sB[tid] = b[tid];

    int node = blockIdx.x * 8 + r;
    float scale = rsqrtf(g_deg[node]);
    sP[r][u] = out[node * UNITS + u] * scale;   // pooled row, scaled
    __syncthreads();

    float acc = sB[u];
    #pragma unroll
    for (int k = 0; k < D_FEAT; k++) {
        acc = fmaf(sP[r][k], sW[k][u], acc);
    }
    out[node * UNITS + u] = fmaxf(acc, 0.0f);
}

// ---------------------------------------------------------------------------
extern "C" void kernel_launch(void* const* d_in, const int* in_sizes, int n_in,
                              void* d_out, int out_size) {
    const float* x      = (const float*)d_in[0];
    const float* W      = (const float*)d_in[1];
    const float* b      = (const float*)d_in[2];
    const int*   source = (const int*)d_in[3];
    const int*   target = (const int*)d_in[4];
    float* out = (float*)d_out;

    float4* pooled4 = (float4*)out;

    const int T = 256;
    k_zero<<<(N_NODES * 16 + T - 1) / T, T>>>(pooled4);
    k_degree<<<(N_EDGES + T - 1) / T, T>>>(target);
    k_normalize<<<(N_NODES * 16 + T - 1) / T, T>>>((const float4*)x);
    k_scatter<<<(N_EDGES * 16 + T - 1) / T, T>>>(source, target, pooled4);
    k_gemm<<<N_NODES / 8, 512>>>(W, b, out);
}

// round 4
// speedup vs baseline: 1.2899x; 1.2899x over previous
#include <cuda_runtime.h>
#include <cuda_bf16.h>

#define N_NODES 100000
#define N_EDGES 1600000
#define D_FEAT  64
#define UNITS   64
#define SCAN_B  1024
#define N_SCANB ((N_NODES + SCAN_B - 1) / SCAN_B)   // 98

// ---- scratch (__device__ globals; no allocations allowed) -----------------
__device__ int   g_deg[N_NODES];
__device__ int   g_excl[N_NODES];        // exclusive scan within block
__device__ int   g_off[N_NODES + 1];     // CSR row offsets
__device__ int   g_cursor[N_NODES];      // mutable copy for reorder
__device__ int   g_bsum[128];
__device__ int   g_boff[128];
__device__ float g_inv[N_NODES];         // rsqrt(deg)
__device__ int   g_sorted_src[N_EDGES];  // sources sorted by target

// ---------------------------------------------------------------------------
__global__ void k_zero_deg() {
    int i = blockIdx.x * blockDim.x + threadIdx.x;
    if (i < N_NODES) g_deg[i] = 0;
}

__global__ void k_degree(const int* __restrict__ target) {
    int e = blockIdx.x * blockDim.x + threadIdx.x;
    if (e < N_EDGES) atomicAdd(&g_deg[target[e]], 1);
}

// ---- exclusive scan of degrees (3 kernels) --------------------------------
__global__ __launch_bounds__(SCAN_B) void k_scan1() {
    __shared__ int sh[SCAN_B];
    int tid = threadIdx.x;
    int i = blockIdx.x * SCAN_B + tid;
    int v = (i < N_NODES) ? g_deg[i] : 0;
    sh[tid] = v;
    __syncthreads();
    #pragma unroll
    for (int ofs = 1; ofs < SCAN_B; ofs <<= 1) {
        int t = (tid >= ofs) ? sh[tid - ofs] : 0;
        __syncthreads();
        sh[tid] += t;
        __syncthreads();
    }
    if (i < N_NODES) g_excl[i] = sh[tid] - v;           // exclusive within block
    if (tid == SCAN_B - 1) g_bsum[blockIdx.x] = sh[tid];
}

__global__ void k_scan2() {   // single block, 128 threads
    __shared__ int sh[128];
    int tid = threadIdx.x;
    int v = (tid < N_SCANB) ? g_bsum[tid] : 0;
    sh[tid] = v;
    __syncthreads();
    #pragma unroll
    for (int ofs = 1; ofs < 128; ofs <<= 1) {
        int t = (tid >= ofs) ? sh[tid - ofs] : 0;
        __syncthreads();
        sh[tid] += t;
        __syncthreads();
    }
    g_boff[tid] = sh[tid] - v;                          // exclusive block offsets
}

__global__ void k_scan3() {
    int i = blockIdx.x * blockDim.x + threadIdx.x;
    if (i < N_NODES) {
        int o = g_excl[i] + g_boff[i >> 10];
        g_off[i] = o;
        g_cursor[i] = o;
        g_inv[i] = rsqrtf((float)g_deg[i]);
    }
    if (i == 0) g_off[N_NODES] = N_EDGES;
}

// ---- counting-sort edge reorder -------------------------------------------
__global__ void k_reorder(const int* __restrict__ source,
                          const int* __restrict__ target) {
    int e = blockIdx.x * blockDim.x + threadIdx.x;
    if (e >= N_EDGES) return;
    int t = target[e];
    int pos = atomicAdd(&g_cursor[t], 1);
    g_sorted_src[pos] = source[e];
}

// ---------------------------------------------------------------------------
// Fused: pooled[n] = inv[n] * sum_{s in edges(n)} inv[s] * x[s]
//        out[n]    = relu(pooled[n] @ W + b)
// warp per node, 4 nodes per warp; block = 1024 threads (32 warps, 128 nodes)
// ---------------------------------------------------------------------------
#define NODES_PER_WARP 4
#define FUSE_THREADS   1024
#define NODES_PER_BLK  (32 * NODES_PER_WARP)   // 128

__global__ __launch_bounds__(FUSE_THREADS) void k_fused(
    const float2* __restrict__ x2,
    const float*  __restrict__ W,
    const float*  __restrict__ b,
    float* __restrict__ out)
{
    __shared__ float sW[D_FEAT * UNITS];   // 16 KB, W[k*64+u]
    __shared__ float sB[UNITS];
    __shared__ float sP[32][D_FEAT];       // one pooled row per warp, 8 KB

    int tid  = threadIdx.x;
    int lane = tid & 31;
    int w    = tid >> 5;

    // cooperative load of W and b
    #pragma unroll
    for (int i = 0; i < (D_FEAT * UNITS) / FUSE_THREADS; i++)
        sW[tid + i * FUSE_THREADS] = W[tid + i * FUSE_THREADS];
    if (tid < UNITS) sB[tid] = b[tid];
    __syncthreads();

    #pragma unroll
    for (int r = 0; r < NODES_PER_WARP; r++) {
        int n = blockIdx.x * NODES_PER_BLK + w * NODES_PER_WARP + r;
        if (n >= N_NODES) return;

        int beg = g_off[n];
        int end = g_off[n + 1];
        float inv_t = g_inv[n];

        float ax = 0.f, ay = 0.f;   // features 2*lane, 2*lane+1
        for (int base = beg; base < end; base += 32) {
            int e = base + lane;
            int sv = (e < end) ? g_sorted_src[e] : 0;
            float iv = (e < end) ? g_inv[sv] : 0.f;
            int cnt = min(32, end - base);
            for (int j = 0; j < cnt; j++) {
                int   s = __shfl_sync(0xffffffff, sv, j);
                float f = __shfl_sync(0xffffffff, iv, j);
                float2 v = x2[s * (D_FEAT / 2) + lane];
                ax = fmaf(f, v.x, ax);
                ay = fmaf(f, v.y, ay);
            }
        }
        sP[w][2 * lane]     = ax * inv_t;
        sP[w][2 * lane + 1] = ay * inv_t;
        __syncwarp();

        // GEMV: lane computes output units (lane) and (lane+32)
        float a0 = sB[lane];
        float a1 = sB[lane + 32];
        #pragma unroll
        for (int k = 0; k < D_FEAT; k++) {
            float pk = sP[w][k];
            a0 = fmaf(pk, sW[k * UNITS + lane],      a0);
            a1 = fmaf(pk, sW[k * UNITS + lane + 32], a1);
        }
        out[n * UNITS + lane]      = fmaxf(a0, 0.f);
        out[n * UNITS + lane + 32] = fmaxf(a1, 0.f);
        __syncwarp();
    }
}

// ---------------------------------------------------------------------------
extern "C" void kernel_launch(void* const* d_in, const int* in_sizes, int n_in,
                              void* d_out, int out_size) {
    const float* x      = (const float*)d_in[0];
    const float* W      = (const float*)d_in[1];
    const float* b      = (const float*)d_in[2];
    const int*   source = (const int*)d_in[3];
    const int*   target = (const int*)d_in[4];
    float* out = (float*)d_out;

    const int T = 256;
    k_zero_deg<<<(N_NODES + T - 1) / T, T>>>();
    k_degree<<<(N_EDGES + T - 1) / T, T>>>(target);
    k_scan1<<<N_SCANB, SCAN_B>>>();
    k_scan2<<<1, 128>>>();
    k_scan3<<<(N_NODES + T - 1) / T, T>>>();
    k_reorder<<<(N_EDGES + T - 1) / T, T>>>(source, target);
    int fuse_blocks = (N_NODES + NODES_PER_BLK - 1) / NODES_PER_BLK;
    k_fused<<<fuse_blocks, FUSE_THREADS>>>((const float2*)x, W, b, out);
}

// round 7
// speedup vs baseline: 1.3798x; 1.0697x over previous
#include <cuda_runtime.h>
#include <cuda_bf16.h>

#define N_NODES 100000
#define N_EDGES 1600000
#define D_FEAT  64
#define UNITS   64
#define SCAN_B  1024
#define N_SCANB ((N_NODES + SCAN_B - 1) / SCAN_B)   // 98

// ---- scratch (__device__ globals; no allocations allowed) -----------------
__device__ int   g_deg[N_NODES];
__device__ int   g_excl[N_NODES];
__device__ int   g_off[N_NODES + 1];
__device__ int   g_cursor[N_NODES];
__device__ int   g_bsum[128];
__device__ int   g_boff[128];
__device__ float g_inv[N_NODES];
__device__ int   g_sorted_src[N_EDGES];

// ---------------------------------------------------------------------------
__global__ void k_zero_deg() {
    int i = blockIdx.x * blockDim.x + threadIdx.x;
    if (i < N_NODES) g_deg[i] = 0;
}

__global__ void k_degree(const int* __restrict__ target) {
    int e = blockIdx.x * blockDim.x + threadIdx.x;
    if (e < N_EDGES) atomicAdd(&g_deg[target[e]], 1);
}

// ---- exclusive scan of degrees (3 kernels) --------------------------------
__global__ __launch_bounds__(SCAN_B) void k_scan1() {
    __shared__ int sh[SCAN_B];
    int tid = threadIdx.x;
    int i = blockIdx.x * SCAN_B + tid;
    int v = (i < N_NODES) ? g_deg[i] : 0;
    sh[tid] = v;
    __syncthreads();
    #pragma unroll
    for (int ofs = 1; ofs < SCAN_B; ofs <<= 1) {
        int t = (tid >= ofs) ? sh[tid - ofs] : 0;
        __syncthreads();
        sh[tid] += t;
        __syncthreads();
    }
    if (i < N_NODES) g_excl[i] = sh[tid] - v;
    if (tid == SCAN_B - 1) g_bsum[blockIdx.x] = sh[tid];
}

// single block, 128 threads: shfl warp-scan + cross-warp fixup
__global__ void k_scan2() {
    __shared__ int warp_tot[4];
    int tid = threadIdx.x;
    int lane = tid & 31;
    int w = tid >> 5;
    int v = (tid < N_SCANB) ? g_bsum[tid] : 0;
    int s = v;
    #pragma unroll
    for (int ofs = 1; ofs < 32; ofs <<= 1) {
        int t = __shfl_up_sync(0xffffffff, s, ofs);
        if (lane >= ofs) s += t;
    }
    if (lane == 31) warp_tot[w] = s;
    __syncthreads();
    int add = 0;
    #pragma unroll
    for (int k = 0; k < 4; k++) if (k < w) add += warp_tot[k];
    g_boff[tid] = s - v + add;   // exclusive
}

__global__ void k_scan3() {
    int i = blockIdx.x * blockDim.x + threadIdx.x;
    if (i < N_NODES) {
        int o = g_excl[i] + g_boff[i >> 10];
        g_off[i] = o;
        g_cursor[i] = o;
        g_inv[i] = rsqrtf((float)g_deg[i]);
    }
    if (i == 0) g_off[N_NODES] = N_EDGES;
}

// ---- counting-sort edge reorder -------------------------------------------
__global__ void k_reorder(const int* __restrict__ source,
                          const int* __restrict__ target) {
    int e = blockIdx.x * blockDim.x + threadIdx.x;
    if (e >= N_EDGES) return;
    int t = target[e];
    int pos = atomicAdd(&g_cursor[t], 1);
    g_sorted_src[pos] = source[e];
}

// ---------------------------------------------------------------------------
// Fused gather + GEMV.
// Warp per node: 16 lanes cover one edge row (float4 each); the two half-
// warps process edges j and j+1 in the same step; dual accumulators break
// the FMA dependency chain.
// ---------------------------------------------------------------------------
#define NODES_PER_WARP 4
#define FUSE_THREADS   1024
#define NODES_PER_BLK  (32 * NODES_PER_WARP)   // 128

__global__ __launch_bounds__(FUSE_THREADS) void k_fused(
    const float4* __restrict__ x4,
    const float*  __restrict__ W,
    const float*  __restrict__ b,
    float* __restrict__ out)
{
    __shared__ float sW[D_FEAT * UNITS];     // 16 KB
    __shared__ float sB[UNITS];
    __shared__ float sP[32][D_FEAT];         // 8 KB, one pooled row per warp

    int tid  = threadIdx.x;
    int lane = tid & 31;
    int w    = tid >> 5;
    int half = lane >> 4;      // 0 or 1: which edge of the pair
    int fl   = lane & 15;      // float4 index within the feature row

    #pragma unroll
    for (int i = 0; i < (D_FEAT * UNITS) / FUSE_THREADS; i++)
        sW[tid + i * FUSE_THREADS] = W[tid + i * FUSE_THREADS];
    if (tid < UNITS) sB[tid] = b[tid];
    __syncthreads();

    #pragma unroll
    for (int r = 0; r < NODES_PER_WARP; r++) {
        int n = blockIdx.x * NODES_PER_BLK + w * NODES_PER_WARP + r;
        if (n >= N_NODES) return;

        int beg = g_off[n];
        int end = g_off[n + 1];
        float inv_t = g_inv[n];

        float4 acc0 = make_float4(0.f, 0.f, 0.f, 0.f);
        float4 acc1 = make_float4(0.f, 0.f, 0.f, 0.f);

        for (int base = beg; base < end; base += 32) {
            int e = base + lane;
            bool valid = e < end;
            int   sv = valid ? g_sorted_src[e] : 0;
            float iv = valid ? g_inv[sv] : 0.f;
            int cnt = min(32, end - base);

            #pragma unroll 2
            for (int j = 0; j < cnt; j += 4) {
                int   s0 = __shfl_sync(0xffffffff, sv, j + half);
                float f0 = __shfl_sync(0xffffffff, iv, j + half);
                int   s1 = __shfl_sync(0xffffffff, sv, j + 2 + half);
                float f1 = __shfl_sync(0xffffffff, iv, j + 2 + half);
                float4 v0 = x4[s0 * (D_FEAT / 4) + fl];
                float4 v1 = x4[s1 * (D_FEAT / 4) + fl];
                acc0.x = fmaf(f0, v0.x, acc0.x);
                acc0.y = fmaf(f0, v0.y, acc0.y);
                acc0.z = fmaf(f0, v0.z, acc0.z);
                acc0.w = fmaf(f0, v0.w, acc0.w);
                acc1.x = fmaf(f1, v1.x, acc1.x);
                acc1.y = fmaf(f1, v1.y, acc1.y);
                acc1.z = fmaf(f1, v1.z, acc1.z);
                acc1.w = fmaf(f1, v1.w, acc1.w);
            }
        }

        // combine dual accumulators, then the two half-warps
        float4 a;
        a.x = acc0.x + acc1.x;
        a.y = acc0.y + acc1.y;
        a.z = acc0.z + acc1.z;
        a.w = acc0.w + acc1.w;
        a.x += __shfl_down_sync(0xffffffff, a.x, 16);
        a.y += __shfl_down_sync(0xffffffff, a.y, 16);
        a.z += __shfl_down_sync(0xffffffff, a.z, 16);
        a.w += __shfl_down_sync(0xffffffff, a.w, 16);
        if (half == 0) {
            float4* sp4 = (float4*)sP[w];
            a.x *= inv_t; a.y *= inv_t; a.z *= inv_t; a.w *= inv_t;
            sp4[fl] = a;
        }
        __syncwarp();

        // GEMV: lane computes output units lane and lane+32
        float a0 = sB[lane];
        float a1 = sB[lane + 32];
        #pragma unroll
        for (int k = 0; k < D_FEAT; k++) {
            float pk = sP[w][k];
            a0 = fmaf(pk, sW[k * UNITS + lane],      a0);
            a1 = fmaf(pk, sW[k * UNITS + lane + 32], a1);
        }
        out[n * UNITS + lane]      = fmaxf(a0, 0.f);
        out[n * UNITS + lane + 32] = fmaxf(a1, 0.f);

        // reset accumulators conceptually handled by redeclaration next r
        __syncwarp();
    }
}

// ---------------------------------------------------------------------------
extern "C" void kernel_launch(void* const* d_in, const int* in_sizes, int n_in,
                              void* d_out, int out_size) {
    const float* x      = (const float*)d_in[0];
    const float* W      = (const float*)d_in[1];
    const float* b      = (const float*)d_in[2];
    const int*   source = (const int*)d_in[3];
    const int*   target = (const int*)d_in[4];
    float* out = (float*)d_out;

    const int T = 256;
    k_zero_deg<<<(N_NODES + T - 1) / T, T>>>();
    k_degree<<<(N_EDGES + T - 1) / T, T>>>(target);
    k_scan1<<<N_SCANB, SCAN_B>>>();
    k_scan2<<<1, 128>>>();
    k_scan3<<<(N_NODES + T - 1) / T, T>>>();
    k_reorder<<<(N_EDGES + T - 1) / T, T>>>(source, target);
    int fuse_blocks = (N_NODES + NODES_PER_BLK - 1) / NODES_PER_BLK;
    k_fused<<<fuse_blocks, FUSE_THREADS>>>((const float4*)x, W, b, out);
}

// round 8
// speedup vs baseline: 1.4423x; 1.0453x over previous
#include <cuda_runtime.h>
#include <cuda_bf16.h>

#define N_NODES 100000
#define N_EDGES 1600000
#define D_FEAT  64
#define UNITS   64
#define SCAN_B  1024
#define N_SCANB ((N_NODES + SCAN_B - 1) / SCAN_B)   // 98

// ---- scratch (__device__ globals; no allocations allowed) -----------------
__device__ int    g_deg[N_NODES];
__device__ int    g_excl[N_NODES];
__device__ int    g_off[N_NODES + 1];
__device__ int    g_cursor[N_NODES];
__device__ int    g_bsum[128];
__device__ int    g_boff[128];
__device__ float  g_inv[N_NODES];
__device__ int    g_sorted_src[N_EDGES];
__device__ float4 g_xnorm[N_NODES * (D_FEAT / 4)];   // 25.6 MB

// ---------------------------------------------------------------------------
__global__ void k_zero_deg() {
    int i = blockIdx.x * blockDim.x + threadIdx.x;
    if (i < N_NODES) g_deg[i] = 0;
}

__global__ void k_degree(const int* __restrict__ target) {
    int e = blockIdx.x * blockDim.x + threadIdx.x;
    if (e < N_EDGES) atomicAdd(&g_deg[target[e]], 1);
}

// ---- exclusive scan of degrees (3 kernels) --------------------------------
__global__ __launch_bounds__(SCAN_B) void k_scan1() {
    __shared__ int sh[SCAN_B];
    int tid = threadIdx.x;
    int i = blockIdx.x * SCAN_B + tid;
    int v = (i < N_NODES) ? g_deg[i] : 0;
    sh[tid] = v;
    __syncthreads();
    #pragma unroll
    for (int ofs = 1; ofs < SCAN_B; ofs <<= 1) {
        int t = (tid >= ofs) ? sh[tid - ofs] : 0;
        __syncthreads();
        sh[tid] += t;
        __syncthreads();
    }
    if (i < N_NODES) g_excl[i] = sh[tid] - v;
    if (tid == SCAN_B - 1) g_bsum[blockIdx.x] = sh[tid];
}

// single block, 128 threads: shfl warp-scan + cross-warp fixup
__global__ void k_scan2() {
    __shared__ int warp_tot[4];
    int tid = threadIdx.x;
    int lane = tid & 31;
    int w = tid >> 5;
    int v = (tid < N_SCANB) ? g_bsum[tid] : 0;
    int s = v;
    #pragma unroll
    for (int ofs = 1; ofs < 32; ofs <<= 1) {
        int t = __shfl_up_sync(0xffffffff, s, ofs);
        if (lane >= ofs) s += t;
    }
    if (lane == 31) warp_tot[w] = s;
    __syncthreads();
    int add = 0;
    #pragma unroll
    for (int k = 0; k < 4; k++) if (k < w) add += warp_tot[k];
    g_boff[tid] = s - v + add;   // exclusive
}

__global__ void k_scan3() {
    int i = blockIdx.x * blockDim.x + threadIdx.x;
    if (i < N_NODES) {
        int o = g_excl[i] + g_boff[i >> 10];
        g_off[i] = o;
        g_cursor[i] = o;
        g_inv[i] = rsqrtf((float)g_deg[i]);
    }
    if (i == 0) g_off[N_NODES] = N_EDGES;
}

// ---- pre-scale features: x_norm[n] = rsqrt(deg[n]) * x[n] -----------------
__global__ void k_normalize(const float4* __restrict__ x4) {
    int i = blockIdx.x * blockDim.x + threadIdx.x;
    if (i >= N_NODES * (D_FEAT / 4)) return;
    float s = g_inv[i >> 4];
    float4 v = x4[i];
    v.x *= s; v.y *= s; v.z *= s; v.w *= s;
    g_xnorm[i] = v;
}

// ---- counting-sort edge reorder -------------------------------------------
__global__ void k_reorder(const int* __restrict__ source,
                          const int* __restrict__ target) {
    int e = blockIdx.x * blockDim.x + threadIdx.x;
    if (e >= N_EDGES) return;
    int t = target[e];
    int pos = atomicAdd(&g_cursor[t], 1);
    g_sorted_src[pos] = source[e];
}

// ---------------------------------------------------------------------------
// Fused gather + GEMV. Warp per node; each 16-lane half-warp owns every other
// edge of the node's CSR row; per edge the half-warp broadcast-loads the
// source index and vector-loads the 256-B x_norm row (float4/lane).
// Unrolled 4 edges deep for MLP; no shuffles in the hot loop.
// ---------------------------------------------------------------------------
#define NODES_PER_WARP 2
#define FUSE_THREADS   1024
#define NODES_PER_BLK  (32 * NODES_PER_WARP)   // 64

__global__ __launch_bounds__(FUSE_THREADS) void k_fused(
    const float*  __restrict__ W,
    const float*  __restrict__ b,
    float* __restrict__ out)
{
    __shared__ float sW[D_FEAT * UNITS];     // 16 KB
    __shared__ float sB[UNITS];
    __shared__ float sP[32][D_FEAT];         // 8 KB, one pooled row per warp

    int tid  = threadIdx.x;
    int lane = tid & 31;
    int w    = tid >> 5;
    int half = lane >> 4;      // which edge of the pair
    int fl   = lane & 15;      // float4 index within feature row

    #pragma unroll
    for (int i = 0; i < (D_FEAT * UNITS) / FUSE_THREADS; i++)
        sW[tid + i * FUSE_THREADS] = W[tid + i * FUSE_THREADS];
    if (tid < UNITS) sB[tid] = b[tid];
    __syncthreads();

    #pragma unroll
    for (int r = 0; r < NODES_PER_WARP; r++) {
        int n = blockIdx.x * NODES_PER_BLK + w * NODES_PER_WARP + r;
        if (n >= N_NODES) return;

        int beg = g_off[n];
        int end = g_off[n + 1];
        float inv_t = g_inv[n];

        float4 acc0 = make_float4(0.f, 0.f, 0.f, 0.f);
        float4 acc1 = make_float4(0.f, 0.f, 0.f, 0.f);

        int e = beg + half;               // this half-warp's stream, stride 2
        // main: 4 edges per iteration (8 per warp)
        for (; e + 6 < end; e += 8) {
            int s0 = g_sorted_src[e];
            int s1 = g_sorted_src[e + 2];
            int s2 = g_sorted_src[e + 4];
            int s3 = g_sorted_src[e + 6];
            float4 v0 = g_xnorm[s0 * 16 + fl];
            float4 v1 = g_xnorm[s1 * 16 + fl];
            float4 v2 = g_xnorm[s2 * 16 + fl];
            float4 v3 = g_xnorm[s3 * 16 + fl];
            acc0.x += v0.x; acc0.y += v0.y; acc0.z += v0.z; acc0.w += v0.w;
            acc1.x += v1.x; acc1.y += v1.y; acc1.z += v1.z; acc1.w += v1.w;
            acc0.x += v2.x; acc0.y += v2.y; acc0.z += v2.z; acc0.w += v2.w;
            acc1.x += v3.x; acc1.y += v3.y; acc1.z += v3.z; acc1.w += v3.w;
        }
        // tail
        for (; e < end; e += 2) {
            int s0 = g_sorted_src[e];
            float4 v0 = g_xnorm[s0 * 16 + fl];
            acc0.x += v0.x; acc0.y += v0.y; acc0.z += v0.z; acc0.w += v0.w;
        }

        float4 a;
        a.x = acc0.x + acc1.x;
        a.y = acc0.y + acc1.y;
        a.z = acc0.z + acc1.z;
        a.w = acc0.w + acc1.w;
        a.x += __shfl_down_sync(0xffffffff, a.x, 16);
        a.y += __shfl_down_sync(0xffffffff, a.y, 16);
        a.z += __shfl_down_sync(0xffffffff, a.z, 16);
        a.w += __shfl_down_sync(0xffffffff, a.w, 16);
        if (half == 0) {
            float4* sp4 = (float4*)sP[w];
            a.x *= inv_t; a.y *= inv_t; a.z *= inv_t; a.w *= inv_t;
            sp4[fl] = a;
        }
        __syncwarp();

        // GEMV: lane computes output units lane and lane+32
        float a0 = sB[lane];
        float a1 = sB[lane + 32];
        #pragma unroll
        for (int k = 0; k < D_FEAT; k++) {
            float pk = sP[w][k];
            a0 = fmaf(pk, sW[k * UNITS + lane],      a0);
            a1 = fmaf(pk, sW[k * UNITS + lane + 32], a1);
        }
        out[n * UNITS + lane]      = fmaxf(a0, 0.f);
        out[n * UNITS + lane + 32] = fmaxf(a1, 0.f);
        __syncwarp();
    }
}

// ---------------------------------------------------------------------------
extern "C" void kernel_launch(void* const* d_in, const int* in_sizes, int n_in,
                              void* d_out, int out_size) {
    const float* x      = (const float*)d_in[0];
    const float* W      = (const float*)d_in[1];
    const float* b      = (const float*)d_in[2];
    const int*   source = (const int*)d_in[3];
    const int*   target = (const int*)d_in[4];
    float* out = (float*)d_out;

    const int T = 256;
    k_zero_deg<<<(N_NODES + T - 1) / T, T>>>();
    k_degree<<<(N_EDGES + T - 1) / T, T>>>(target);
    k_scan1<<<N_SCANB, SCAN_B>>>();
    k_scan2<<<1, 128>>>();
    k_scan3<<<(N_NODES + T - 1) / T, T>>>();
    k_normalize<<<(N_NODES * 16 + T - 1) / T, T>>>((const float4*)x);
    k_reorder<<<(N_EDGES + T - 1) / T, T>>>(source, target);
    int fuse_blocks = (N_NODES + NODES_PER_BLK - 1) / NODES_PER_BLK;
    k_fused<<<fuse_blocks, FUSE_THREADS>>>(W, b, out);
}